// round 7
// baseline (speedup 1.0000x reference)
#include <cuda_runtime.h>

#define HH 1024
#define WW 1024
#define BATCH 16
#define NIMG (HH*WW)
#define NTEN (BATCH*NIMG)
#define RS 32                       // output rows per warp sweep
#define NSTRIP 9                    // strips of 120 useful cols (overlap 8)
#define NBAND (HH/RS)               // 32
#define WPI (NSTRIP*NBAND)          // 288 warps per image
#define NIMGS (2*BATCH)             // 32
#define TOTW (WPI*NIMGS)            // 9216 warps
#define NBLK (TOTW/4)               // 2304 blocks of 128 threads
#define FULLM 0xffffffffu

__device__ float g_buf0[2*NTEN];
__device__ float g_buf1[2*NTEN];
__device__ double g_pp[TOTW];
__device__ double g_ps[TOTW];

__device__ __forceinline__ float PINF() { return __int_as_float(0x7f800000); }
__device__ __forceinline__ float NINF() { return __int_as_float(0xff800000); }
__device__ __forceinline__ float min3(float a, float b, float c) { return fminf(a, fminf(b, c)); }
__device__ __forceinline__ float max3(float a, float b, float c) { return fmaxf(a, fmaxf(b, c)); }

// Fused double soft-skeletonize step. One warp = one 128-col strip (4 cols per
// lane as float4) swept over RS+8 rows. Stage 1 computes skeleton iteration i,
// stage 2 consumes stage-1 rows (2-iteration register delay) to compute
// iteration i+1. Strips overlap by 8 cols; only interior cols 4..123
// (lanes 1..30) are written — these are exactly the columns whose 2-stage
// dependency cone stays inside the loaded 128 columns. Image-boundary padding
// (+inf for min input, -inf mask on min-pool output) is applied per position.
template<bool FINAL>
__global__ __launch_bounds__(128, 4)
void skel2_kernel(const float* __restrict__ in0, const float* __restrict__ in1,
                  float* __restrict__ dst,
                  const float* __restrict__ oth0, const float* __restrict__ oth1)
{
    const int lane  = threadIdx.x & 31;
    const int wid   = blockIdx.x * 4 + (threadIdx.x >> 5);
    const int strip = wid % NSTRIP;
    const int band  = (wid / NSTRIP) % NBAND;
    const int img   = wid / WPI;
    const int t = img >> 4;
    const int b = img & 15;

    const float* src = (t == 0 ? in0 : in1) + (size_t)b * NIMG;
    const float* oth = FINAL ? ((t == 0 ? oth0 : oth1) + (size_t)b * NIMG) : (const float*)0;
    float* out = FINAL ? (float*)0 : dst + (size_t)t * NTEN + (size_t)b * NIMG;

    const int base = strip * 120 - 4;
    const int gX   = base + 4 * lane;
    const int r0   = band * RS;
    const bool ldok = (gX >= 0) && (gX + 3 < WW);
    const bool wrok = (lane >= 1) && (lane <= 30) && (gX + 3 < WW);
    bool cok[4];
    #pragma unroll
    for (int j = 0; j < 4; j++) cok[j] = ((gX + j) >= 0) && ((gX + j) < WW);

    // rolling state: stage 1 and stage 2
    float h1A[4], h1B[4], g1A[4], g1B[4], m1C[4], x2A[4], x2B[4];
    float h2A[4], h2B[4], g2A[4], g2B[4], m2C[4], s2A[4], s2B[4];
    #pragma unroll
    for (int j = 0; j < 4; j++) {
        h1A[j] = PINF(); h1B[j] = PINF(); g1A[j] = NINF(); g1B[j] = NINF();
        m1C[j] = 0.f; x2A[j] = 0.f; x2B[j] = 0.f;
        h2A[j] = PINF(); h2B[j] = PINF(); g2A[j] = NINF(); g2B[j] = NINF();
        m2C[j] = 0.f; s2A[j] = 0.f; s2B[j] = 0.f;
    }
    float accp = 0.f, accs = 0.f;

    #pragma unroll 4
    for (int k = 0; k < RS + 8; k++) {
        const int rr = r0 - 4 + k;
        const bool rv0 = (rr >= 0) && (rr < HH);
        float4 A;
        if (rv0 && ldok) A = *(const float4*)(src + ((long)rr * WW + gX));
        else             A = make_float4(PINF(), PINF(), PINF(), PINF());

        // ── stage 1: horizontal 3-min (shuffle edges) ──
        float xm1 = __shfl_up_sync(FULLM, A.w, 1);
        float xp4 = __shfl_down_sync(FULLM, A.x, 1);
        float h1Cv[4];
        h1Cv[0] = min3(xm1, A.x, A.y);  h1Cv[1] = min3(A.x, A.y, A.z);
        h1Cv[2] = min3(A.y, A.z, A.w);  h1Cv[3] = min3(A.z, A.w, xp4);
        // vertical 3-min centered rr-1, mask outside-image to -inf
        const bool rv1 = ((rr - 1) >= 0) && ((rr - 1) < HH);
        float m1[4], m1M[4];
        #pragma unroll
        for (int j = 0; j < 4; j++) {
            m1[j]  = min3(h1A[j], h1B[j], h1Cv[j]);
            m1M[j] = (rv1 && cok[j]) ? m1[j] : NINF();
        }
        float mm1 = __shfl_up_sync(FULLM, m1M[3], 1);
        float mp1 = __shfl_down_sync(FULLM, m1M[0], 1);
        float g1Cv[4];
        g1Cv[0] = max3(mm1,   m1M[0], m1M[1]);  g1Cv[1] = max3(m1M[0], m1M[1], m1M[2]);
        g1Cv[2] = max3(m1M[1], m1M[2], m1M[3]); g1Cv[3] = max3(m1M[2], m1M[3], mp1);
        // stage-1 skeleton row rr-2 (PINF outside image so stage-2 min-pool pads right)
        const bool rv2 = ((rr - 2) >= 0) && ((rr - 2) < HH);
        float s1[4];
        #pragma unroll
        for (int j = 0; j < 4; j++) {
            float mp      = max3(g1A[j], g1B[j], g1Cv[j]);
            float contour = fmaxf(mp - m1C[j], 0.f);
            float raw     = fmaxf(x2A[j] - contour, 0.f);
            s1[j] = (rv2 && cok[j]) ? raw : PINF();
        }
        // rotate stage 1
        #pragma unroll
        for (int j = 0; j < 4; j++) {
            h1A[j] = h1B[j]; h1B[j] = h1Cv[j];
            g1A[j] = g1B[j]; g1B[j] = g1Cv[j];
            m1C[j] = m1[j];
            x2A[j] = x2B[j];
        }
        x2B[0] = A.x; x2B[1] = A.y; x2B[2] = A.z; x2B[3] = A.w;

        // ── stage 2: same pipeline on s1 (row rr-2) ──
        float sm1 = __shfl_up_sync(FULLM, s1[3], 1);
        float sp1 = __shfl_down_sync(FULLM, s1[0], 1);
        float h2Cv[4];
        h2Cv[0] = min3(sm1, s1[0], s1[1]);  h2Cv[1] = min3(s1[0], s1[1], s1[2]);
        h2Cv[2] = min3(s1[1], s1[2], s1[3]); h2Cv[3] = min3(s1[2], s1[3], sp1);
        const bool rv3 = ((rr - 3) >= 0) && ((rr - 3) < HH);
        float m2[4], m2M[4];
        #pragma unroll
        for (int j = 0; j < 4; j++) {
            m2[j]  = min3(h2A[j], h2B[j], h2Cv[j]);
            m2M[j] = (rv3 && cok[j]) ? m2[j] : NINF();
        }
        float nm1 = __shfl_up_sync(FULLM, m2M[3], 1);
        float np1 = __shfl_down_sync(FULLM, m2M[0], 1);
        float g2Cv[4];
        g2Cv[0] = max3(nm1,   m2M[0], m2M[1]);  g2Cv[1] = max3(m2M[0], m2M[1], m2M[2]);
        g2Cv[2] = max3(m2M[1], m2M[2], m2M[3]); g2Cv[3] = max3(m2M[2], m2M[3], np1);

        if (k >= 8) {
            const int orow = rr - 4;         // stage-2 output row
            float o[4];
            #pragma unroll
            for (int j = 0; j < 4; j++) {
                float mp      = max3(g2A[j], g2B[j], g2Cv[j]);
                float contour = fmaxf(mp - m2C[j], 0.f);
                o[j] = fmaxf(s2A[j] - contour, 0.f);
            }
            if (FINAL) {
                if (wrok) {
                    const float4 ov = *(const float4*)(oth + ((long)orow * WW + gX));
                    accp += o[0]*ov.x + o[1]*ov.y + o[2]*ov.z + o[3]*ov.w;
                    accs += o[0] + o[1] + o[2] + o[3];
                }
            } else {
                if (wrok)
                    *(float4*)(out + ((long)orow * WW + gX)) =
                        make_float4(o[0], o[1], o[2], o[3]);
            }
        }
        // rotate stage 2
        #pragma unroll
        for (int j = 0; j < 4; j++) {
            h2A[j] = h2B[j]; h2B[j] = h2Cv[j];
            g2A[j] = g2B[j]; g2B[j] = g2Cv[j];
            m2C[j] = m2[j];
            s2A[j] = s2B[j]; s2B[j] = s1[j];
        }
    }

    if (FINAL) {
        double p = (double)accp, s = (double)accs;
        #pragma unroll
        for (int off = 16; off; off >>= 1) {
            p += __shfl_down_sync(FULLM, p, off);
            s += __shfl_down_sync(FULLM, s, off);
        }
        if (lane == 0) { g_pp[wid] = p; g_ps[wid] = s; }
    }
}

__global__ void finish_kernel(float* __restrict__ out)
{
    __shared__ double sp0[8], ss0[8], sp1[8], ss1[8];
    double a0 = 0, c0 = 0, a1 = 0, c1 = 0;
    for (int i = threadIdx.x; i < TOTW; i += 256) {
        int img = i / WPI;
        double pp = g_pp[i], ss = g_ps[i];
        if ((img >> 4) == 0) { a0 += pp; c0 += ss; }
        else                 { a1 += pp; c1 += ss; }
    }
    #pragma unroll
    for (int off = 16; off; off >>= 1) {
        a0 += __shfl_down_sync(FULLM, a0, off);
        c0 += __shfl_down_sync(FULLM, c0, off);
        a1 += __shfl_down_sync(FULLM, a1, off);
        c1 += __shfl_down_sync(FULLM, c1, off);
    }
    const int lane = threadIdx.x & 31, w = threadIdx.x >> 5;
    if (lane == 0) { sp0[w] = a0; ss0[w] = c0; sp1[w] = a1; ss1[w] = c1; }
    __syncthreads();
    if (threadIdx.x == 0) {
        double P0 = 0, S0 = 0, P1 = 0, S1 = 0;
        #pragma unroll
        for (int i = 0; i < 8; i++) { P0 += sp0[i]; S0 += ss0[i]; P1 += sp1[i]; S1 += ss1[i]; }
        double iflat = (P0 + 1.0) / (S0 + 1.0);   // sum(skelP*gt)/sum(skelP)
        double tflat = (P1 + 1.0) / (S1 + 1.0);   // sum(skelG*pred)/sum(skelG)
        out[0] = (float)(1.0 - 2.0 * iflat * tflat / (iflat + tflat));
    }
}

extern "C" void kernel_launch(void* const* d_in, const int* in_sizes, int n_in,
                              void* d_out, int out_size)
{
    const float* pred = (const float*)d_in[0];
    const float* gt   = (const float*)d_in[1];
    float* out = (float*)d_out;

    float *b0 = 0, *b1 = 0;
    cudaGetSymbolAddress((void**)&b0, g_buf0);
    cudaGetSymbolAddress((void**)&b1, g_buf1);

    // 20 skeleton iterations = 10 fused double-steps.
    // Pass 0 reads harness inputs.
    skel2_kernel<false><<<NBLK, 128>>>(pred, gt, b0, (const float*)0, (const float*)0);

    float* cur = b0;
    float* nxt = b1;
    for (int p = 1; p < 9; p++) {
        skel2_kernel<false><<<NBLK, 128>>>(cur, cur + NTEN, nxt, (const float*)0, (const float*)0);
        float* tmp = cur; cur = nxt; nxt = tmp;
    }

    // Final fused pass: iterations 18+19, reduced against the counterpart tensor.
    skel2_kernel<true><<<NBLK, 128>>>(cur, cur + NTEN, (float*)0, gt, pred);

    finish_kernel<<<1, 256>>>(out);
}

// round 8
// speedup vs baseline: 1.3598x; 1.3598x over previous
#include <cuda_runtime.h>

#define HH 1024
#define WW 1024
#define BATCH 16
#define NIMG (HH*WW)
#define NTEN (BATCH*NIMG)
#define RS 64                       // output rows per warp sweep
#define NBAND (HH/RS)               // 16
#define FULLM 0xffffffffu
#define TOTW 4096                   // 8 strips * 16 bands * 32 images

__device__ float g_buf0[2*NTEN];
__device__ float g_buf1[2*NTEN];
__device__ double g_pp[TOTW];
__device__ double g_ps[TOTW];

__device__ __forceinline__ float PINF() { return __int_as_float(0x7f800000); }
__device__ __forceinline__ float NINF() { return __int_as_float(0xff800000); }
__device__ __forceinline__ float min3(float a, float b, float c) { return fminf(a, fminf(b, c)); }
__device__ __forceinline__ float max3(float a, float b, float c) { return fmaxf(a, fmaxf(b, c)); }

// Rolling state for the separable 3x3 min-pool -> 3x3 max-pool pipeline.
struct St {
    float hA[4], hB[4];      // horizontal-min rows (rr-2, rr-1)
    float gA[4], gB[4];      // vertical-max candidate rows
    float mC[4];             // min-pool value at the output row (unmasked)
    float hlA, hlB, hrA, hrB;// edge-lane horizontal mins (left/right halo)
    float4 xA, xB;           // input delay line (x at output row)
};

__device__ __forceinline__ void st_init(St& S) {
    #pragma unroll
    for (int j = 0; j < 4; j++) {
        S.hA[j] = PINF(); S.hB[j] = PINF();
        S.gA[j] = NINF(); S.gB[j] = NINF();
        S.mC[j] = 0.f;
    }
    S.hlA = PINF(); S.hlB = PINF(); S.hrA = PINF(); S.hrB = PINF();
    S.xA = make_float4(0.f, 0.f, 0.f, 0.f);
    S.xB = S.xA;
}

// Process one input row (global row rr). Produces the skeleton output for row
// rr-2 (valid once the pipeline is full). VEDGE=false: no row-bounds checks.
template<bool VEDGE>
__device__ __forceinline__ float4 advance(St& S, int lane, int rr,
                                          bool leftok, bool rightok,
                                          float4 A, float xl2, float xl1,
                                          float xr0, float xr1)
{
    // horizontal 3-min (shuffles carry cross-lane edges)
    float xm1 = __shfl_up_sync(FULLM, A.w, 1);
    if (lane == 0) xm1 = xl1;
    float xp4 = __shfl_down_sync(FULLM, A.x, 1);
    if (lane == 31) xp4 = xr0;
    float hC[4];
    hC[0] = min3(xm1, A.x, A.y);  hC[1] = min3(A.x, A.y, A.z);
    hC[2] = min3(A.y, A.z, A.w);  hC[3] = min3(A.z, A.w, xp4);
    float hlC = min3(xl2, xl1, A.x);
    float hrC = min3(A.w, xr0, xr1);

    // vertical 3-min centered at row rr-1; mask to -inf outside image
    float m[4], mM[4];
    const bool rvC = (!VEDGE) || (((rr - 1) >= 0) && ((rr - 1) < HH));
    #pragma unroll
    for (int j = 0; j < 4; j++) {
        m[j]  = min3(S.hA[j], S.hB[j], hC[j]);
        mM[j] = rvC ? m[j] : NINF();
    }
    float ml = min3(S.hlA, S.hlB, hlC);
    float mr = min3(S.hrA, S.hrB, hrC);
    float mlM = (leftok  && rvC) ? ml : NINF();
    float mrM = (rightok && rvC) ? mr : NINF();

    // horizontal 3-max over the min-pool row
    float mm1 = __shfl_up_sync(FULLM, mM[3], 1);
    if (lane == 0) mm1 = mlM;
    float mp4 = __shfl_down_sync(FULLM, mM[0], 1);
    if (lane == 31) mp4 = mrM;
    float gC[4];
    gC[0] = max3(mm1,  mM[0], mM[1]);  gC[1] = max3(mM[0], mM[1], mM[2]);
    gC[2] = max3(mM[1], mM[2], mM[3]); gC[3] = max3(mM[2], mM[3], mp4);

    // output for row rr-2
    float4 o;
    o.x = fmaxf(S.xA.x - fmaxf(max3(S.gA[0], S.gB[0], gC[0]) - S.mC[0], 0.f), 0.f);
    o.y = fmaxf(S.xA.y - fmaxf(max3(S.gA[1], S.gB[1], gC[1]) - S.mC[1], 0.f), 0.f);
    o.z = fmaxf(S.xA.z - fmaxf(max3(S.gA[2], S.gB[2], gC[2]) - S.mC[2], 0.f), 0.f);
    o.w = fmaxf(S.xA.w - fmaxf(max3(S.gA[3], S.gB[3], gC[3]) - S.mC[3], 0.f), 0.f);

    // rotate
    #pragma unroll
    for (int j = 0; j < 4; j++) {
        S.hA[j] = S.hB[j]; S.hB[j] = hC[j];
        S.gA[j] = S.gB[j]; S.gB[j] = gC[j];
        S.mC[j] = m[j];
    }
    S.hlA = S.hlB; S.hlB = hlC;
    S.hrA = S.hrB; S.hrB = hrC;
    S.xA = S.xB; S.xB = A;
    return o;
}

template<bool VEDGE>
__device__ __forceinline__ void load_row(const float* __restrict__ src, int rr,
                                         int gX, int c0, int lane,
                                         bool leftok, bool rightok,
                                         float4& A, float& xl2, float& xl1,
                                         float& xr0, float& xr1)
{
    const bool rv = (!VEDGE) || ((rr >= 0) && (rr < HH));
    if (rv) A = *(const float4*)(src + ((long)rr * WW + gX));
    else    A = make_float4(PINF(), PINF(), PINF(), PINF());
    xl2 = PINF(); xl1 = PINF(); xr0 = PINF(); xr1 = PINF();
    if (lane == 0 && leftok && rv) {
        float2 tt = *(const float2*)(src + ((long)rr * WW + c0 - 2));
        xl2 = tt.x; xl1 = tt.y;
    }
    if (lane == 31 && rightok && rv) {
        float2 tt = *(const float2*)(src + ((long)rr * WW + c0 + 128));
        xr0 = tt.x; xr1 = tt.y;
    }
}

template<bool VEDGE, bool FINAL>
__device__ __forceinline__ void sweep(const float* __restrict__ src,
                                      float* __restrict__ out,
                                      const float* __restrict__ oth,
                                      int c0, int gX, int r0, int lane,
                                      bool leftok, bool rightok,
                                      float& accp, float& accs)
{
    St S;
    st_init(S);

    // prologue: rows r0-2 .. r0+1 (fill pipeline, no emit)
    #pragma unroll
    for (int k = 0; k < 4; k++) {
        float4 A; float xl2, xl1, xr0, xr1;
        load_row<VEDGE>(src, r0 - 2 + k, gX, c0, lane, leftok, rightok, A, xl2, xl1, xr0, xr1);
        (void)advance<VEDGE>(S, lane, r0 - 2 + k, leftok, rightok, A, xl2, xl1, xr0, xr1);
    }
    // main: rows r0+2 .. r0+RS+1 -> emit rows r0 .. r0+RS-1
    #pragma unroll 6
    for (int k = 0; k < RS; k++) {
        const int rr = r0 + 2 + k;
        float4 A; float xl2, xl1, xr0, xr1;
        load_row<VEDGE>(src, rr, gX, c0, lane, leftok, rightok, A, xl2, xl1, xr0, xr1);
        float4 o = advance<VEDGE>(S, lane, rr, leftok, rightok, A, xl2, xl1, xr0, xr1);
        const int orow = r0 + k;
        if (FINAL) {
            const float4 ov = *(const float4*)(oth + ((long)orow * WW + gX));
            accp += o.x * ov.x + o.y * ov.y + o.z * ov.z + o.w * ov.w;
            accs += o.x + o.y + o.z + o.w;
        } else {
            *(float4*)(out + ((long)orow * WW + gX)) = o;
        }
    }
}

template<bool FINAL>
__global__ __launch_bounds__(128, 8)
void skel_kernel(const float* __restrict__ in0, const float* __restrict__ in1,
                 float* __restrict__ dst,
                 const float* __restrict__ oth0, const float* __restrict__ oth1)
{
    const int lane  = threadIdx.x & 31;
    const int warp  = threadIdx.x >> 5;
    const int strip = blockIdx.y * 4 + warp;      // 0..7 (128 cols each)
    const int band  = blockIdx.x;                 // 0..15
    const int img   = blockIdx.z;                 // 0..31
    const int t = img >> 4;
    const int b = img & 15;

    const float* src = (t == 0 ? in0 : in1) + (size_t)b * NIMG;
    const float* oth = FINAL ? ((t == 0 ? oth0 : oth1) + (size_t)b * NIMG) : (const float*)0;
    float* out = FINAL ? (float*)0 : dst + (size_t)t * NTEN + (size_t)b * NIMG;

    const int c0 = strip * 128;
    const int gX = c0 + 4 * lane;
    const int r0 = band * RS;
    const bool leftok  = (strip > 0);
    const bool rightok = (strip < 7);

    float accp = 0.f, accs = 0.f;
    if (band == 0 || band == NBAND - 1)
        sweep<true,  FINAL>(src, out, oth, c0, gX, r0, lane, leftok, rightok, accp, accs);
    else
        sweep<false, FINAL>(src, out, oth, c0, gX, r0, lane, leftok, rightok, accp, accs);

    if (FINAL) {
        double p = (double)accp, s = (double)accs;
        #pragma unroll
        for (int off = 16; off; off >>= 1) {
            p += __shfl_down_sync(FULLM, p, off);
            s += __shfl_down_sync(FULLM, s, off);
        }
        if (lane == 0) {
            const int wid = img * 128 + blockIdx.y * 64 + band * 4 + warp;
            g_pp[wid] = p;
            g_ps[wid] = s;
        }
    }
}

__global__ void finish_kernel(float* __restrict__ out)
{
    __shared__ double sp0[8], ss0[8], sp1[8], ss1[8];
    double a0 = 0, c0 = 0, a1 = 0, c1 = 0;
    for (int i = threadIdx.x; i < TOTW; i += 256) {
        const int img = i >> 7;     // 128 warps per image
        double pp = g_pp[i], ss = g_ps[i];
        if ((img >> 4) == 0) { a0 += pp; c0 += ss; }
        else                 { a1 += pp; c1 += ss; }
    }
    #pragma unroll
    for (int off = 16; off; off >>= 1) {
        a0 += __shfl_down_sync(FULLM, a0, off);
        c0 += __shfl_down_sync(FULLM, c0, off);
        a1 += __shfl_down_sync(FULLM, a1, off);
        c1 += __shfl_down_sync(FULLM, c1, off);
    }
    const int lane = threadIdx.x & 31, w = threadIdx.x >> 5;
    if (lane == 0) { sp0[w] = a0; ss0[w] = c0; sp1[w] = a1; ss1[w] = c1; }
    __syncthreads();
    if (threadIdx.x == 0) {
        double P0 = 0, S0 = 0, P1 = 0, S1 = 0;
        #pragma unroll
        for (int i = 0; i < 8; i++) { P0 += sp0[i]; S0 += ss0[i]; P1 += sp1[i]; S1 += ss1[i]; }
        double iflat = (P0 + 1.0) / (S0 + 1.0);   // sum(skelP*gt)/sum(skelP)
        double tflat = (P1 + 1.0) / (S1 + 1.0);   // sum(skelG*pred)/sum(skelG)
        out[0] = (float)(1.0 - 2.0 * iflat * tflat / (iflat + tflat));
    }
}

extern "C" void kernel_launch(void* const* d_in, const int* in_sizes, int n_in,
                              void* d_out, int out_size)
{
    const float* pred = (const float*)d_in[0];
    const float* gt   = (const float*)d_in[1];
    float* out = (float*)d_out;

    float *b0 = 0, *b1 = 0;
    cudaGetSymbolAddress((void**)&b0, g_buf0);
    cudaGetSymbolAddress((void**)&b1, g_buf1);

    dim3 grid(NBAND, 2, 2 * BATCH);   // (16, 2, 32) = 1024 blocks of 128 thr
    const int threads = 128;

    // Iteration 0 reads the harness inputs.
    skel_kernel<false><<<grid, threads>>>(pred, gt, b0, (const float*)0, (const float*)0);

    // Iterations 1..18 ping-pong scratch.
    float* cur = b0;
    float* nxt = b1;
    for (int i = 1; i < 19; i++) {
        skel_kernel<false><<<grid, threads>>>(cur, cur + NTEN, nxt, (const float*)0, (const float*)0);
        float* tmp = cur; cur = nxt; nxt = tmp;
    }

    // Iteration 19 fused with the reductions.
    skel_kernel<true><<<grid, threads>>>(cur, cur + NTEN, (float*)0, gt, pred);

    finish_kernel<<<1, 256>>>(out);
}